// round 1
// baseline (speedup 1.0000x reference)
#include <cuda_runtime.h>
#include <math.h>

#define NB 2048
#define NC 32
#define DD 64
#define AA 8

// exp1[n][m] = -0.25 * sum_d (c_n[d]-c_m[d])^2 / l[d]^2   (batch-independent)
__device__ float g_exp1[NC * NC];

__global__ void prep_kernel(const float* __restrict__ centers,
                            const float* __restrict__ ls) {
    int t = threadIdx.x;           // 1024 threads = 32x32 pairs
    int n = t >> 5, m = t & 31;
    float acc = 0.f;
#pragma unroll
    for (int d = 0; d < DD; ++d) {
        float df = centers[n * DD + d] - centers[m * DD + d];
        float l = ls[d];
        acc += (df * df) / (l * l);
    }
    g_exp1[t] = -0.25f * acc;
}

// In-place Cholesky of 64x64 SPD matrix in smem (lower triangle result).
__device__ __forceinline__ void cholesky64(float (*A)[DD + 1], int tid) {
    for (int k = 0; k < DD; ++k) {
        if (tid == 0) A[k][k] = sqrtf(A[k][k]);
        __syncthreads();
        float invd = 1.0f / A[k][k];
        if (tid < DD - 1 - k) {
            int i = k + 1 + tid;
            A[i][k] *= invd;
        }
        __syncthreads();
        // trailing rank-1 update, 16x16 threads, 4x4 regs each
        int ty = tid >> 4, tx = tid & 15;
        float ajk[4], aik[4];
#pragma unroll
        for (int u = 0; u < 4; ++u) {
            int j = k + 1 + tx + 16 * u;
            ajk[u] = (j < DD) ? A[j][k] : 0.f;
            int i = k + 1 + ty + 16 * u;
            aik[u] = (i < DD) ? A[i][k] : 0.f;
        }
#pragma unroll
        for (int ii = 0; ii < 4; ++ii) {
            int i = k + 1 + ty + 16 * ii;
            if (i < DD) {
#pragma unroll
                for (int jj = 0; jj < 4; ++jj) {
                    int j = k + 1 + tx + 16 * jj;
                    if (j < DD && j <= i) A[i][j] -= aik[ii] * ajk[jj];
                }
            }
        }
        __syncthreads();
    }
}

// Solve L Y = X in-place (X is 64 x 32).
__device__ __forceinline__ void fwd_solve(const float (*A)[DD + 1],
                                          float (*X)[NC + 1], int tid) {
    int c = tid & 31, r0 = tid >> 5;
    for (int k = 0; k < DD; ++k) {
        if (tid < NC) X[k][tid] /= A[k][k];
        __syncthreads();
        float xk = X[k][c];
        for (int i = k + 1 + r0; i < DD; i += 8) X[i][c] -= A[i][k] * xk;
        __syncthreads();
    }
}

// Solve L^T Z = Y in-place.
__device__ __forceinline__ void bwd_solve(const float (*A)[DD + 1],
                                          float (*X)[NC + 1], int tid) {
    int c = tid & 31, r0 = tid >> 5;
    for (int k = DD - 1; k >= 0; --k) {
        if (tid < NC) X[k][tid] /= A[k][k];
        __syncthreads();
        float xk = X[k][c];
        for (int i = r0; i < k; i += 8) X[i][c] -= A[k][i] * xk;
        __syncthreads();
    }
}

__global__ __launch_bounds__(256) void rbf_kernel(
    const float* __restrict__ mean, const float* __restrict__ cov,
    const float* __restrict__ centers, const float* __restrict__ weights,
    const float* __restrict__ ls,
    float* __restrict__ out_am, float* __restrict__ out_ac,
    float* __restrict__ out_cc) {
    __shared__ float A[DD][DD + 1];     // working matrix (B_mat, then B_q)
    __shared__ float X[DD][NC + 1];     // RHS / solutions (D-major)
    __shared__ float Dm[DD][NC + 1];    // d_n = c_n - mean, transposed
    __shared__ float CC[DD][AA];        // cross_cov pre-squash
    __shared__ float G[NC][NC + 1];     // Gram -> Q
    __shared__ float W[NC][AA];
    __shared__ float pw[NC][AA];        // phi*W, later P = Q W
    __shared__ float phi[NC];
    __shared__ float smean[DD], sinvl[DD], sl2[DD];
    __shared__ float ldiag[DD];
    __shared__ float s_scal[2];         // [0]=normalizer, [1]=c_q
    __shared__ float s_am[AA], s_dc[AA], s_cd[AA];
    __shared__ float R8[AA][AA + 1];
    __shared__ float ACm[AA][AA + 1];
    __shared__ float gd[NC];

    const int tid = threadIdx.x;
    const int b = blockIdx.x;
    const float* covb = cov + (size_t)b * DD * DD;
    const float* meanb = mean + (size_t)b * DD;

    if (tid < DD) {
        float l = ls[tid];
        smean[tid] = meanb[tid];
        sinvl[tid] = 1.0f / l;
        sl2[tid] = l * l;
    }
    {
        int n = tid >> 3, a = tid & 7;   // 256 threads cover 32x8 exactly
        W[n][a] = weights[tid];
    }
    __syncthreads();

    // Dm[d][n] = centers[n][d] - mean[d];  B_mat = diag(invl) cov diag(invl) + I
    for (int idx = tid; idx < NC * DD; idx += 256) {
        int n = idx >> 6, d = idx & 63;
        Dm[d][n] = centers[idx] - smean[d];
    }
    for (int idx = tid; idx < DD * DD; idx += 256) {
        int i = idx >> 6, j = idx & 63;
        float v = covb[idx] * sinvl[i] * sinvl[j];
        if (i == j) v += 1.0f;
        A[i][j] = v;
    }
    __syncthreads();
    // X = scaled_inp^T
    for (int idx = tid; idx < DD * NC; idx += 256) {
        int d = idx >> 5, n = idx & 31;
        X[d][n] = Dm[d][n] * sinvl[d];
    }
    __syncthreads();

    cholesky64(A, tid);
    if (tid < DD) ldiag[tid] = logf(A[tid][tid]);
    fwd_solve(A, X, tid);
    bwd_solve(A, X, tid);   // X now holds t^T = B_mat^{-1} scaled_inp^T

    if (tid == 0) {
        float s = 0.f;
        for (int i = 0; i < DD; ++i) s += ldiag[i];
        s_scal[0] = expf(-s);   // exp(-0.5*logdet), logdet = 2*sum(log Lii)
    }
    __syncthreads();

    // phi[n] = normalizer * exp(-0.5 * sum_d scaled[n][d]*t[n][d])
    if (tid < NC) {
        float acc = 0.f;
        for (int d = 0; d < DD; ++d) acc += Dm[d][tid] * sinvl[d] * X[d][tid];
        phi[tid] = expf(-0.5f * acc) * s_scal[0];
    }
    __syncthreads();
    {
        int n = tid >> 3, a = tid & 7;
        pw[n][a] = phi[n] * W[n][a];
    }
    __syncthreads();
    if (tid < AA) {
        float s = 0.f;
        for (int n = 0; n < NC; ++n) s += pw[n][tid];
        s_am[tid] = s;   // raw action_mean
    }
    // cross_cov[d][a] = invl[d] * sum_n t^T[d][n] * (phi W)[n][a]
    for (int idx = tid; idx < DD * AA; idx += 256) {
        int d = idx >> 3, a = idx & 7;
        float acc = 0.f;
        for (int n = 0; n < NC; ++n) acc += X[d][n] * pw[n][a];
        CC[d][a] = acc * sinvl[d];
    }
    __syncthreads();

    // ---- Phase 2: B_q = cov + diag(l^2/2) ----
    for (int idx = tid; idx < DD * DD; idx += 256) {
        int i = idx >> 6, j = idx & 63;
        float v = covb[idx];
        if (i == j) v += 0.5f * sl2[i];
        A[i][j] = v;
    }
    for (int idx = tid; idx < DD * NC; idx += 256) {
        int d = idx >> 5, n = idx & 31;
        X[d][n] = Dm[d][n];
    }
    __syncthreads();
    cholesky64(A, tid);
    // c_q = exp(0.5*sum log(l^2/2) - sum log Lq_ii)
    if (tid < DD) ldiag[tid] = 0.5f * logf(0.5f * sl2[tid]) - logf(A[tid][tid]);
    fwd_solve(A, X, tid);   // X = L^{-1} D
    if (tid == 0) {
        float s = 0.f;
        for (int i = 0; i < DD; ++i) s += ldiag[i];
        s_scal[1] = expf(s);
    }
    __syncthreads();

    // G = X^T X  (32x32)
    for (int p = tid; p < NC * NC; p += 256) {
        int n = p >> 5, m = p & 31;
        float acc = 0.f;
        for (int d = 0; d < DD; ++d) acc += X[d][n] * X[d][m];
        G[n][m] = acc;
    }
    __syncthreads();
    if (tid < NC) gd[tid] = G[tid][tid];
    __syncthreads();
    // Q[n][m] = c_q * exp(exp1 - (G_nn + 2 G_nm + G_mm)/8)   (overwrite G)
    {
        float cq = s_scal[1];
        for (int p = tid; p < NC * NC; p += 256) {
            int n = p >> 5, m = p & 31;
            G[n][m] = cq * expf(g_exp1[p] - 0.125f * (gd[n] + 2.0f * G[n][m] + gd[m]));
        }
    }
    __syncthreads();
    // P = Q W  (32x8) into pw
    {
        int n = tid >> 3, c = tid & 7;
        float acc = 0.f;
        for (int m = 0; m < NC; ++m) acc += G[n][m] * W[m][c];
        pw[n][c] = acc;
    }
    __syncthreads();
    // R = W^T P (8x8)
    if (tid < AA * AA) {
        int a = tid >> 3, c = tid & 7;
        float acc = 0.f;
        for (int n = 0; n < NC; ++n) acc += W[n][a] * pw[n][c];
        R8[a][c] = acc;
    }
    __syncthreads();
    if (tid < AA * AA) {
        int a = tid >> 3, c = tid & 7;
        float v = 0.5f * (R8[a][c] + R8[c][a]) - s_am[a] * s_am[c];
        if (a == c) v += 1e-6f;
        ACm[a][c] = v;
    }
    __syncthreads();

    // ---- squash_sin (max_action = 1) ----
    if (tid < AA) {
        float dc = ACm[tid][tid];
        float e = expf(-0.5f * dc);
        s_dc[tid] = dc;
        s_cd[tid] = e * cosf(s_am[tid]);           // diag of C
        out_am[(size_t)b * AA + tid] = e * sinf(s_am[tid]);
    }
    __syncthreads();
    if (tid < AA * AA) {
        int a = tid >> 3, c = tid & 7;
        float lq = -0.5f * (s_dc[a] + s_dc[c]);
        float q = expf(lq);
        float v = ACm[a][c];
        float sq = 0.5f * ((expf(lq + v) - q) * cosf(s_am[a] - s_am[c])
                         - (expf(lq - v) - q) * cosf(s_am[a] + s_am[c]));
        out_ac[(size_t)b * AA * AA + tid] = sq;
    }
    for (int idx = tid; idx < DD * AA; idx += 256) {
        int c = idx & 7;
        out_cc[(size_t)b * DD * AA + idx] = CC[idx >> 3][c] * s_cd[c];
    }
}

extern "C" void kernel_launch(void* const* d_in, const int* in_sizes, int n_in,
                              void* d_out, int out_size) {
    const float* mean = (const float*)d_in[0];
    const float* cov = (const float*)d_in[1];
    const float* centers = (const float*)d_in[2];
    const float* weights = (const float*)d_in[3];
    const float* ls = (const float*)d_in[4];
    float* out = (float*)d_out;

    int B = in_sizes[0] / DD;   // 2048
    float* out_am = out;
    float* out_ac = out + (size_t)B * AA;
    float* out_cc = out + (size_t)B * AA + (size_t)B * AA * AA;

    prep_kernel<<<1, 1024>>>(centers, ls);
    rbf_kernel<<<B, 256>>>(mean, cov, centers, weights, ls, out_am, out_ac, out_cc);
}